// round 17
// baseline (speedup 1.0000x reference)
#include <cuda_runtime.h>
#include <math.h>
#include <stdint.h>

#define NB   64
#define CIN  256
#define COUT 256
#define HH   56
#define HW   (HH * HH)         // 3136
#define NWORDS 8
#define TAPS 9
#define KW   (TAPS * NWORDS)   // 72 k-words
#define EPSC 1e-5
#define NSLICE 8

__device__ float        g_scale[CIN];
__device__ float        g_shift[CIN];
__device__ double       g_part[CIN * NSLICE * 2];
__device__ unsigned int g_xbits[(size_t)NB * HW * NWORDS];     // [n][pix][word]
__device__ unsigned int g_wkt[KW * COUT];                      // k-major: [k][co]
__device__ int          g_w9[COUT * TAPS];                     // popc of weight tap group

// single-LOP3 3-input ops
__device__ __forceinline__ unsigned int xor3(unsigned int a, unsigned int b, unsigned int c) {
    unsigned int r;
    asm("lop3.b32 %0, %1, %2, %3, 0x96;" : "=r"(r) : "r"(a), "r"(b), "r"(c));
    return r;
}
__device__ __forceinline__ unsigned int maj3(unsigned int a, unsigned int b, unsigned int c) {
    unsigned int r;
    asm("lop3.b32 %0, %1, %2, %3, 0xE8;" : "=r"(r) : "r"(a), "r"(b), "r"(c));
    return r;
}

// ---------------------------------------------------------------------------
// 1) BN stats stage 1: fp32 per-thread partials, double reduction.
// ---------------------------------------------------------------------------
__global__ void bn_stats1_kernel(const float* __restrict__ x) {
    const int c = blockIdx.x, slice = blockIdx.y, nper = NB / NSLICE;
    float fs = 0.f, fs2 = 0.f;
    for (int n = slice * nper; n < (slice + 1) * nper; ++n) {
        const float4* p = (const float4*)(x + ((size_t)n * CIN + c) * HW);
        for (int i = threadIdx.x; i < HW / 4; i += blockDim.x) {
            float4 v = p[i];
            fs  += v.x + v.y + v.z + v.w;
            fs2 += v.x * v.x + v.y * v.y + v.z * v.z + v.w * v.w;
        }
    }
    double s = (double)fs, s2 = (double)fs2;
    __shared__ double ws[32], ws2[32];
    #pragma unroll
    for (int o = 16; o > 0; o >>= 1) {
        s  += __shfl_down_sync(0xffffffffu, s,  o);
        s2 += __shfl_down_sync(0xffffffffu, s2, o);
    }
    const int warp = threadIdx.x >> 5, lane = threadIdx.x & 31;
    if (lane == 0) { ws[warp] = s; ws2[warp] = s2; }
    __syncthreads();
    if (warp == 0) {
        const int nw = blockDim.x >> 5;
        s  = (lane < nw) ? ws[lane]  : 0.0;
        s2 = (lane < nw) ? ws2[lane] : 0.0;
        #pragma unroll
        for (int o = 16; o > 0; o >>= 1) {
            s  += __shfl_down_sync(0xffffffffu, s,  o);
            s2 += __shfl_down_sync(0xffffffffu, s2, o);
        }
        if (lane == 0) {
            g_part[(c * NSLICE + slice) * 2 + 0] = s;
            g_part[(c * NSLICE + slice) * 2 + 1] = s2;
        }
    }
}

// ---------------------------------------------------------------------------
// 2) FUSED: weight bit-pack (k-major) + tap popcounts + bn stage-2 (block 0).
// ---------------------------------------------------------------------------
__global__ void packw_bn2_kernel(const float* __restrict__ w,
                                 const float* __restrict__ gamma,
                                 const float* __restrict__ beta) {
    if (blockIdx.x == 0 && threadIdx.x < CIN) {
        const int c = threadIdx.x;
        double s = 0.0, s2 = 0.0;
        #pragma unroll
        for (int k = 0; k < NSLICE; ++k) {
            s  += g_part[(c * NSLICE + k) * 2 + 0];
            s2 += g_part[(c * NSLICE + k) * 2 + 1];
        }
        const double Nt = (double)NB * (double)HW;
        double mean = s / Nt;
        double var  = s2 / Nt - mean * mean;
        float sc = (float)(1.0 / sqrt(var + EPSC)) * gamma[c];
        g_scale[c] = sc;
        g_shift[c] = beta[c] - (float)mean * sc;
    }
    const int idx = blockIdx.x * blockDim.x + threadIdx.x;   // COUT*72, word fastest
    if (idx >= COUT * KW) return;
    const int word = idx & 7;
    const int tap  = (idx >> 3) % TAPS;
    const int co   = idx / KW;
    const float* p = w + ((size_t)co * CIN + word * 32) * TAPS + tap;
    unsigned int bits = 0;
    #pragma unroll
    for (int j = 0; j < 32; ++j)
        if (p[(size_t)j * TAPS] > 0.0f) bits |= (1u << j);
    g_wkt[(tap * NWORDS + word) * COUT + co] = bits;
    int pc = __popc(bits);
    #pragma unroll
    for (int o = 4; o > 0; o >>= 1)
        pc += __shfl_down_sync(0xffffffffu, pc, o, 8);
    if (word == 0) g_w9[co * TAPS + tap] = pc;
}

// ---------------------------------------------------------------------------
// 3) Binarize + bit-pack activations.
// ---------------------------------------------------------------------------
__global__ void pack_x_kernel(const float* __restrict__ x) {
    const int idx = blockIdx.x * blockDim.x + threadIdx.x;
    if (idx >= NB * NWORDS * HW) return;
    const int s    = idx % HW;
    const int t    = idx / HW;
    const int word = t & 7;
    const int n    = t >> 3;
    const int cbase = word * 32;
    const float* p = x + ((size_t)(n * CIN + cbase)) * HW + s;
    unsigned int bits = 0;
    #pragma unroll
    for (int j = 0; j < 32; ++j) {
        float xh = fmaf(p[(size_t)j * HW], g_scale[cbase + j], g_shift[cbase + j]);
        if (xh > 0.0f) bits |= (1u << j);
    }
    g_xbits[((size_t)n * HW + s) * NWORDS + word] = bits;
}

// ---------------------------------------------------------------------------
// 4) GEMM-tiled XNOR conv with carry-save compression:
//    9 taps' term-words -> 4 popcounts (2-level full-adder tree, lop3).
//    Block: 64 px x 64 co, 256 threads, thread tile 4x4.
//    Borders: x pre-zeroed; epilogue corrects via g_w9 table (R1-proven).
// ---------------------------------------------------------------------------
#define MPIX 64
#define NCO  64
#define OFF_XS 0
#define OFF_WS (KW * MPIX)
#define OFF_W9 (KW * MPIX + KW * NCO)
#define OFF_SB (OFF_W9 + NCO * TAPS)
#define SMEM_CONV ((OFF_SB + NCO) * 4)

__global__ void __launch_bounds__(256, 2)
bconv_kernel(const float* __restrict__ bias, float* __restrict__ out) {
    extern __shared__ unsigned int sm[];
    unsigned int* sxs = sm + OFF_XS;
    unsigned int* sws = sm + OFF_WS;
    int*          sw9 = (int*)(sm + OFF_W9);
    float*        sb  = (float*)(sm + OFF_SB);

    const int tid = threadIdx.x;
    const int p0  = blockIdx.x * MPIX;
    const int co0 = blockIdx.y * NCO;
    const int n   = blockIdx.z;

    // weights (k-major sub-columns)
    {
        const uint4* src = (const uint4*)(g_wkt);
        uint4* dst = (uint4*)sws;
        for (int i = tid; i < KW * (NCO / 4); i += 256) {
            const int k = i >> 4, q = i & 15;
            dst[k * (NCO / 4) + q] = src[(k * COUT + co0) / 4 + q];
        }
    }
    // x im2col (invalid taps -> 0)
    const unsigned int* xb = g_xbits + (size_t)n * HW * NWORDS;
    for (int i = tid; i < KW * MPIX; i += 256) {
        const int k = i >> 6, j = i & 63;
        const int tap = k >> 3, word = k & 7;
        const int dh = tap / 3 - 1, dw = tap % 3 - 1;
        const int p = p0 + j;
        const int h = p / HH, w = p % HH;
        const int hh = h + dh, ww = w + dw;
        const bool valid = (hh >= 0) & (hh < HH) & (ww >= 0) & (ww < HH);
        sxs[i] = valid ? xb[((size_t)hh * HH + ww) * NWORDS + word] : 0u;
    }
    // weight tap popcounts + bias
    for (int i = tid; i < NCO * TAPS; i += 256) {
        const int co = i / TAPS, tp = i % TAPS;
        sw9[co * TAPS + tp] = g_w9[(co0 + co) * TAPS + tp];
    }
    if (tid < NCO) sb[tid] = bias[co0 + tid];
    __syncthreads();

    const int pj = (tid & 15) * 4;   // 4 pixels
    const int cj = (tid >> 4) * 4;   // 4 c_out

    int acc[4][4];
    #pragma unroll
    for (int i = 0; i < 4; ++i)
        #pragma unroll
        for (int j = 0; j < 4; ++j) acc[i][j] = 0;

    #pragma unroll 1
    for (int wd = 0; wd < NWORDS; ++wd) {
        uint4 xv[TAPS], wv[TAPS];
        #pragma unroll
        for (int tap = 0; tap < TAPS; ++tap) {
            xv[tap] = *(const uint4*)(sxs + (tap * NWORDS + wd) * MPIX + pj);
            wv[tap] = *(const uint4*)(sws + (tap * NWORDS + wd) * NCO + cj);
        }
        #pragma unroll
        for (int i = 0; i < 4; ++i) {
            #pragma unroll
            for (int j = 0; j < 4; ++j) {
                unsigned int t0 = ((const unsigned int*)&xv[0])[i] ^ ((const unsigned int*)&wv[0])[j];
                unsigned int t1 = ((const unsigned int*)&xv[1])[i] ^ ((const unsigned int*)&wv[1])[j];
                unsigned int t2 = ((const unsigned int*)&xv[2])[i] ^ ((const unsigned int*)&wv[2])[j];
                unsigned int t3 = ((const unsigned int*)&xv[3])[i] ^ ((const unsigned int*)&wv[3])[j];
                unsigned int t4 = ((const unsigned int*)&xv[4])[i] ^ ((const unsigned int*)&wv[4])[j];
                unsigned int t5 = ((const unsigned int*)&xv[5])[i] ^ ((const unsigned int*)&wv[5])[j];
                unsigned int t6 = ((const unsigned int*)&xv[6])[i] ^ ((const unsigned int*)&wv[6])[j];
                unsigned int t7 = ((const unsigned int*)&xv[7])[i] ^ ((const unsigned int*)&wv[7])[j];
                unsigned int t8 = ((const unsigned int*)&xv[8])[i] ^ ((const unsigned int*)&wv[8])[j];
                // level 1: three full adders
                unsigned int s1 = xor3(t0, t1, t2), c1 = maj3(t0, t1, t2);
                unsigned int s2 = xor3(t3, t4, t5), c2 = maj3(t3, t4, t5);
                unsigned int s3 = xor3(t6, t7, t8), c3 = maj3(t6, t7, t8);
                // level 2
                unsigned int S  = xor3(s1, s2, s3), C1 = maj3(s1, s2, s3);
                unsigned int C2 = xor3(c1, c2, c3), D  = maj3(c1, c2, c3);
                // n = pc(S) + 2*(pc(C1)+pc(C2)) + 4*pc(D)
                acc[i][j] += __popc(S) + 2 * (__popc(C1) + __popc(C2)) + 4 * __popc(D);
            }
        }
    }

    // epilogue with border correction
    #pragma unroll
    for (int i = 0; i < 4; ++i) {
        const int p = p0 + pj + i;
        const int h = p / HH, w = p % HH;
        unsigned int invmask = 0;
        #pragma unroll
        for (int tap = 0; tap < TAPS; ++tap) {
            const int hh = h + tap / 3 - 1, ww = w + tap % 3 - 1;
            if (!((hh >= 0) & (hh < HH) & (ww >= 0) & (ww < HH))) invmask |= (1u << tap);
        }
        const int nv = TAPS - __popc(invmask);
        const int base = CIN * nv;
        float* op = out + (size_t)n * COUT * HW + p;
        #pragma unroll
        for (int j = 0; j < 4; ++j) {
            const int co = cj + j;
            int corr = 0;
            if (invmask) {
                unsigned int m = invmask;
                while (m) {
                    const int tp = __ffs(m) - 1;
                    m &= m - 1;
                    corr += sw9[co * TAPS + tp];
                }
            }
            const float y = (float)(base - 2 * acc[i][j] + 2 * corr) + sb[co];
            op[(size_t)(co0 + co) * HW] = fmaxf(y, 0.0f);
        }
    }
}

// ---------------------------------------------------------------------------
extern "C" void kernel_launch(void* const* d_in, const int* in_sizes, int n_in,
                              void* d_out, int out_size) {
    const float* x     = (const float*)d_in[0];
    const float* gamma = (const float*)d_in[1];
    const float* beta  = (const float*)d_in[2];
    const float* w     = (const float*)d_in[3];
    const float* b     = (const float*)d_in[4];
    float* out = (float*)d_out;

    dim3 sgrid(CIN, NSLICE);
    bn_stats1_kernel<<<sgrid, 256>>>(x);

    packw_bn2_kernel<<<(COUT * KW + 255) / 256, 256>>>(w, gamma, beta);

    const int pxn = NB * NWORDS * HW;
    pack_x_kernel<<<(pxn + 255) / 256, 256>>>(x);

    cudaFuncSetAttribute(bconv_kernel,
                         cudaFuncAttributeMaxDynamicSharedMemorySize, SMEM_CONV);
    dim3 grid(HW / MPIX, COUT / NCO, NB);   // 49 x 4 x 64
    bconv_kernel<<<grid, 256, SMEM_CONV>>>(b, out);
}